// round 2
// baseline (speedup 1.0000x reference)
#include <cuda_runtime.h>
#include <math.h>

typedef unsigned long long ULL;

// ---------------------------------------------------------------------------
// Problem constants: B=16, dim=48, hid=16, C=8, H=W=256, HW=65536
// Total pixels = B*HW = 1,048,576.
// t = x viewed as (B, HW, 48) row-major (pure reshape of (B,48,256,256)).
// ---------------------------------------------------------------------------

#define HW 65536
#define NB 16
#define DIM 48
#define HID 16
#define NC 8

// Scratch (allocation-free rule: __device__ globals). 33.5 MB each.
__device__ __align__(16) float g_n [NB * NC * HW];    // planar (B, C, HW) — layernormed x2
__device__ __align__(16) float g_x1[NB * HW * NC];    // (B, HW, C) — gate branch

// ---- packed f32x2 helpers (sm_103a) ----
__device__ __forceinline__ ULL pk(float a, float b) {
    ULL r; asm("mov.b64 %0,{%1,%2};" : "=l"(r) : "f"(a), "f"(b)); return r;
}
__device__ __forceinline__ void upk(ULL v, float& a, float& b) {
    asm("mov.b64 {%0,%1},%2;" : "=f"(a), "=f"(b) : "l"(v));
}
__device__ __forceinline__ ULL f2fma(ULL a, ULL b, ULL c) {
    ULL d; asm("fma.rn.f32x2 %0,%1,%2,%3;" : "=l"(d) : "l"(a), "l"(b), "l"(c)); return d;
}
__device__ __forceinline__ ULL f2mul(ULL a, ULL b) {
    ULL d; asm("mul.rn.f32x2 %0,%1,%2;" : "=l"(d) : "l"(a), "l"(b)); return d;
}
__device__ __forceinline__ ULL f2add(ULL a, ULL b) {
    ULL d; asm("add.rn.f32x2 %0,%1,%2;" : "=l"(d) : "l"(a), "l"(b)); return d;
}

__device__ __forceinline__ float gelu_exact(float v) {
    return 0.5f * v * (1.0f + erff(v * 0.70710678118654752f));
}

// ---------------------------------------------------------------------------
// Kernel A: per pixel: h = gelu(gelu(x@W1 + b1)); x1 = h[0:8] -> g_x1;
//           n = LN(h[8:16])*gamma+beta -> g_n (planar).
// 2 pixels per thread (amortize weight LDS), GEMM in f32x2 pairs over j.
// ---------------------------------------------------------------------------
__device__ __forceinline__ void finishA(ULL* acc, size_t P,
                                        const float* b1s, const float* gs, const float* bs) {
    float h[16];
#pragma unroll
    for (int j = 0; j < 8; j++) upk(acc[j], h[2 * j], h[2 * j + 1]);
#pragma unroll
    for (int i = 0; i < 16; i++) h[i] = gelu_exact(gelu_exact(h[i] + b1s[i]));

    // x1 store: (B,HW,C) contiguous 8 floats
    float4 s0 = make_float4(h[0], h[1], h[2], h[3]);
    float4 s1 = make_float4(h[4], h[5], h[6], h[7]);
    ((float4*)g_x1)[P * 2]     = s0;
    ((float4*)g_x1)[P * 2 + 1] = s1;

    // layernorm over h[8..15]
    float m = 0.0f;
#pragma unroll
    for (int c = 0; c < 8; c++) m += h[8 + c];
    m *= 0.125f;
    float v = 0.0f;
#pragma unroll
    for (int c = 0; c < 8; c++) { float d = h[8 + c] - m; v += d * d; }
    v *= 0.125f;
    float inv = rsqrtf(v + 1e-5f);

    size_t b_ = P >> 16, pp = P & 65535;
    float* nb = g_n + (b_ << 19) + pp;          // b*8*65536
#pragma unroll
    for (int c = 0; c < 8; c++)
        nb[(size_t)c << 16] = (h[8 + c] - m) * inv * gs[c] + bs[c];
}

__global__ void __launch_bounds__(256) kA(const float* __restrict__ x,
                                          const float* __restrict__ W1,
                                          const float* __restrict__ b1,
                                          const float* __restrict__ gamma,
                                          const float* __restrict__ beta) {
    __shared__ __align__(16) ULL   w1s[384];   // [k][j2] pairs, k*8+j2
    __shared__ float b1s[16], gs[8], bs[8];

    int tid = threadIdx.x;
    const ULL* w1u = (const ULL*)W1;
    w1s[tid] = w1u[tid];
    if (tid < 128) w1s[256 + tid] = w1u[256 + tid];
    if (tid < 16) b1s[tid] = b1[tid];
    if (tid < 8) { gs[tid] = gamma[tid]; bs[tid] = beta[tid]; }
    __syncthreads();

    size_t P0 = (size_t)blockIdx.x * 512 + tid;   // pixel 0
    size_t P1 = P0 + 256;                          // pixel 1
    const float4* xp0 = (const float4*)(x + P0 * 48);
    const float4* xp1 = (const float4*)(x + P1 * 48);

    ULL a0[8], a1[8];
#pragma unroll
    for (int j = 0; j < 8; j++) { a0[j] = 0ULL; a1[j] = 0ULL; }

#pragma unroll
    for (int kc = 0; kc < 6; kc++) {
        float4 u0 = xp0[kc * 2], u1 = xp0[kc * 2 + 1];
        float4 v0 = xp1[kc * 2], v1 = xp1[kc * 2 + 1];
        float X0[8] = {u0.x, u0.y, u0.z, u0.w, u1.x, u1.y, u1.z, u1.w};
        float X1[8] = {v0.x, v0.y, v0.z, v0.w, v1.x, v1.y, v1.z, v1.w};
#pragma unroll
        for (int kk = 0; kk < 8; kk++) {
            int k = kc * 8 + kk;
            ULL bx0 = pk(X0[kk], X0[kk]);
            ULL bx1 = pk(X1[kk], X1[kk]);
#pragma unroll
            for (int j = 0; j < 8; j++) {
                ULL w = w1s[k * 8 + j];
                a0[j] = f2fma(bx0, w, a0[j]);
                a1[j] = f2fma(bx1, w, a1[j]);
            }
        }
    }
    finishA(a0, P0, b1s, gs, bs);
    finishA(a1, P1, b1s, gs, bs);
}

// ---------------------------------------------------------------------------
// Kernel B: one block = one (b,h) row; 128 threads, each does pixel pair
// (w0, w0+1) packed in f32x2 lanes. dw conv reuses overlapping 3x3 windows,
// pw + GEMM2 in f32x2 with weight LDS shared by the pixel pair.
// ---------------------------------------------------------------------------
__global__ void __launch_bounds__(128) kB(const float* __restrict__ dw_w,
                                          const float* __restrict__ dw_b,
                                          const float* __restrict__ pw_w,
                                          const float* __restrict__ pw_b,
                                          const float* __restrict__ W2,
                                          const float* __restrict__ b2,
                                          float* __restrict__ out) {
    __shared__ __align__(16) float ns[8][3][264];   // [c][row][1+w], cols 0/257 zero halo
    __shared__ __align__(16) ULL   dwp[72], pwp[64], w2s[192], b2s[24];
    __shared__ float dwbs[8], pwbs[8];

    int t = threadIdx.x;
    if (t < 72) { float v = dw_w[t]; dwp[t] = pk(v, v); }
    if (t < 64) { float v = pw_w[t]; pwp[t] = pk(v, v); }
    {
        const ULL* w2u = (const ULL*)W2;
        w2s[t] = w2u[t];
        if (t < 64) w2s[128 + t] = w2u[128 + t];
    }
    if (t < 24) b2s[t] = ((const ULL*)b2)[t];
    if (t < 8) { dwbs[t] = dw_b[t]; pwbs[t] = pw_b[t]; }

    int b_ = blockIdx.x >> 8;
    int h  = blockIdx.x & 255;
    const float* nbase = g_n + ((size_t)b_ << 19);

#pragma unroll
    for (int c = 0; c < 8; c++) {
#pragma unroll
        for (int r = 0; r < 3; r++) {
            int hs = h + r - 1;
            float2 v = make_float2(0.f, 0.f);
            if ((unsigned)hs < 256u)
                v = ((const float2*)(nbase + ((size_t)c << 16) + ((size_t)hs << 8)))[t];
            ns[c][r][1 + 2 * t] = v.x;
            ns[c][r][2 + 2 * t] = v.y;
        }
    }
    if (t == 0) {
#pragma unroll
        for (int c = 0; c < 8; c++)
#pragma unroll
            for (int r = 0; r < 3; r++) { ns[c][r][0] = 0.f; ns[c][r][257] = 0.f; }
    }
    __syncthreads();

    int w0 = 2 * t;

    // depthwise 3x3 (SAME): packed pair = (value for px0, value for px1)
    ULL spp[8], ncp[8];
#pragma unroll
    for (int c = 0; c < 8; c++) {
        ULL acc = 0ULL, center = 0ULL;
#pragma unroll
        for (int r = 0; r < 3; r++) {
            ULL v01 = *(const ULL*)&ns[c][r][w0];       // cols (w0-1, w0)
            ULL v23 = *(const ULL*)&ns[c][r][w0 + 2];   // cols (w0+1, w0+2)
            ULL v12 = (v01 >> 32) | (v23 << 32);        // cols (w0,   w0+1)
            acc = f2fma(v01, dwp[c * 9 + r * 3 + 0], acc);
            acc = f2fma(v12, dwp[c * 9 + r * 3 + 1], acc);
            acc = f2fma(v23, dwp[c * 9 + r * 3 + 2], acc);
            if (r == 1) center = v12;                   // (n[px0][c], n[px1][c])
        }
        spp[c] = f2add(acc, pk(dwbs[c], dwbs[c]));
        ncp[c] = center;
    }

    // pointwise 1x1
    ULL chp[8];
#pragma unroll
    for (int c = 0; c < 8; c++) {
        ULL acc = pk(pwbs[c], pwbs[c]);
#pragma unroll
        for (int c2 = 0; c2 < 8; c2++) acc = f2fma(ncp[c2], pwp[c * 8 + c2], acc);
        chp[c] = acc;
    }

    // gate: g = x1 * sp * ch
    size_t P0 = ((size_t)b_ << 16) + ((size_t)h << 8) + (size_t)w0;
    const float4* x1v = (const float4*)(g_x1 + P0 * 8);
    float4 A = x1v[0], Bv = x1v[1], Cc = x1v[2], D = x1v[3];
    float x10[8] = {A.x, A.y, A.z, A.w, Bv.x, Bv.y, Bv.z, Bv.w};
    float x11[8] = {Cc.x, Cc.y, Cc.z, Cc.w, D.x, D.y, D.z, D.w};
    ULL gp[8];
#pragma unroll
    for (int c = 0; c < 8; c++)
        gp[c] = f2mul(pk(x10[c], x11[c]), f2mul(spp[c], chp[c]));

    // GEMM2: out[d] = sum_c g[c]*W2[c][d] + b2[d]; split d into two halves (regs)
    float* ob = out + (((size_t)b_ * 48) << 16) + ((size_t)h << 8) + (size_t)w0;
#pragma unroll
    for (int half = 0; half < 2; half++) {
        ULL o0[12], o1[12];
#pragma unroll
        for (int j = 0; j < 12; j++) { o0[j] = b2s[half * 12 + j]; o1[j] = o0[j]; }
#pragma unroll
        for (int c = 0; c < 8; c++) {
            float gg0, gg1; upk(gp[c], gg0, gg1);
            ULL gb0 = pk(gg0, gg0), gb1 = pk(gg1, gg1);
#pragma unroll
            for (int j = 0; j < 12; j++) {
                ULL wv = w2s[c * 24 + half * 12 + j];
                o0[j] = f2fma(gb0, wv, o0[j]);
                o1[j] = f2fma(gb1, wv, o1[j]);
            }
        }
#pragma unroll
        for (int j = 0; j < 12; j++) {
            float p00, p01, p10, p11;
            upk(o0[j], p00, p01);   // px0: d=2jj, 2jj+1
            upk(o1[j], p10, p11);   // px1
            int d0 = half * 24 + 2 * j;
            *((float2*)(ob + ((size_t)d0 << 16)))       = make_float2(p00, p10);
            *((float2*)(ob + ((size_t)(d0 + 1) << 16))) = make_float2(p01, p11);
        }
    }
}

// ---------------------------------------------------------------------------
extern "C" void kernel_launch(void* const* d_in, const int* in_sizes, int n_in,
                              void* d_out, int out_size) {
    const float* x     = (const float*)d_in[0];
    const float* W1    = (const float*)d_in[1];
    const float* b1    = (const float*)d_in[2];
    const float* gamma = (const float*)d_in[3];
    const float* beta  = (const float*)d_in[4];
    const float* dw_w  = (const float*)d_in[5];
    const float* dw_b  = (const float*)d_in[6];
    const float* pw_w  = (const float*)d_in[7];
    const float* pw_b  = (const float*)d_in[8];
    const float* W2    = (const float*)d_in[9];
    const float* b2    = (const float*)d_in[10];
    float* out = (float*)d_out;

    // Kernel A: B*HW = 1,048,576 pixels, 512 px/block -> 2048 blocks
    kA<<<2048, 256>>>(x, W1, b1, gamma, beta);
    // Kernel B: one block per (b, h) row, 128 threads (2 px each)
    kB<<<4096, 128>>>(dw_w, dw_b, pw_w, pw_b, W2, b2, out);
}

// round 3
// speedup vs baseline: 1.1308x; 1.1308x over previous
#include <cuda_runtime.h>
#include <math.h>

typedef unsigned long long ULL;

// ---------------------------------------------------------------------------
// B=16, dim=48, hid=16, C=8, H=W=256, HW=65536. Total pixels = 1,048,576.
// ---------------------------------------------------------------------------
#define HW 65536
#define NB 16

// Scratch (allocation-free rule: __device__ globals). 33.5 MB each.
__device__ __align__(16) float g_n [NB * 8 * HW];   // planar (B, C, HW) — LN'd x2
__device__ __align__(16) float g_x1[NB * HW * 8];   // (B, HW, C) — gate branch

// Weights in constant memory (uniform access -> LDCU path, no LDS pressure)
__constant__ ULL   cW1p[384];   // W1 (48,16) as pairs [k*8 + j2]
__constant__ ULL   cW2p[192];   // W2 (8,48)  as pairs [c*24 + d2]
__constant__ float cdw[72];     // dw_w (8,1,3,3)
__constant__ float cpw[64];     // pw_w (8,8)
__constant__ float cb1[16];
__constant__ float cgam[8], cbet[8], cdwb[8], cpwb[8];
__constant__ ULL   cb2p[24];    // b2 (48) as pairs

// ---- packed f32x2 helpers (sm_103a) ----
__device__ __forceinline__ ULL pk(float a, float b) {
    ULL r; asm("mov.b64 %0,{%1,%2};" : "=l"(r) : "f"(a), "f"(b)); return r;
}
__device__ __forceinline__ void upk(ULL v, float& a, float& b) {
    asm("mov.b64 {%0,%1},%2;" : "=f"(a), "=f"(b) : "l"(v));
}
__device__ __forceinline__ ULL f2fma(ULL a, ULL b, ULL c) {
    ULL d; asm("fma.rn.f32x2 %0,%1,%2,%3;" : "=l"(d) : "l"(a), "l"(b), "l"(c)); return d;
}
__device__ __forceinline__ ULL f2mul(ULL a, ULL b) {
    ULL d; asm("mul.rn.f32x2 %0,%1,%2;" : "=l"(d) : "l"(a), "l"(b)); return d;
}
__device__ __forceinline__ ULL f2add(ULL a, ULL b) {
    ULL d; asm("add.rn.f32x2 %0,%1,%2;" : "=l"(d) : "l"(a), "l"(b)); return d;
}

__device__ __forceinline__ float gelu_exact(float v) {
    return 0.5f * v * (1.0f + erff(v * 0.70710678118654752f));
}

// ---------------------------------------------------------------------------
// Kernel A: coalesced smem staging of x, then per-pixel
// h = gelu(gelu(x@W1+b1)); x1=h[0:8]; n=LN(h[8:16])*gamma+beta (planar).
// 128 threads = 128 pixels per block; 8192 blocks.
// smem layout: pixel p's float4 chunk f stored at slot p*12 + (f+p)%12
// (rotation makes the strided read-back ~bank-conflict-free).
// ---------------------------------------------------------------------------
__global__ void __launch_bounds__(128) kA(const float* __restrict__ x) {
    __shared__ __align__(16) float4 xs4[128 * 12];   // 24 KB

    int t = threadIdx.x;
    size_t Pbase = (size_t)blockIdx.x * 128;
    const float4* gx = (const float4*)(x + Pbase * 48);

#pragma unroll
    for (int i = 0; i < 12; i++) {
        int idx = i * 128 + t;          // 0..1535
        int p = idx / 12;
        int f = idx - p * 12;
        int fr = f + p; fr %= 12;
        xs4[p * 12 + fr] = gx[idx];
    }
    __syncthreads();

    // GEMM1: 8 f32x2 accumulators (16 outputs)
    ULL acc[8];
#pragma unroll
    for (int j = 0; j < 8; j++) acc[j] = 0ULL;

    int r0 = t % 12;
#pragma unroll
    for (int f = 0; f < 12; f++) {
        int fr = f + r0; if (fr >= 12) fr -= 12;
        float4 v = xs4[t * 12 + fr];
        float kv[4] = {v.x, v.y, v.z, v.w};
#pragma unroll
        for (int q = 0; q < 4; q++) {
            int k = f * 4 + q;
            ULL bx = pk(kv[q], kv[q]);
#pragma unroll
            for (int j = 0; j < 8; j++)
                acc[j] = f2fma(bx, cW1p[k * 8 + j], acc[j]);
        }
    }

    // epilogue
    float h[16];
#pragma unroll
    for (int j = 0; j < 8; j++) upk(acc[j], h[2 * j], h[2 * j + 1]);
#pragma unroll
    for (int i = 0; i < 16; i++) h[i] = gelu_exact(gelu_exact(h[i] + cb1[i]));

    size_t P = Pbase + (size_t)t;
    ((float4*)g_x1)[P * 2]     = make_float4(h[0], h[1], h[2], h[3]);
    ((float4*)g_x1)[P * 2 + 1] = make_float4(h[4], h[5], h[6], h[7]);

    float m = 0.0f;
#pragma unroll
    for (int c = 0; c < 8; c++) m += h[8 + c];
    m *= 0.125f;
    float var = 0.0f;
#pragma unroll
    for (int c = 0; c < 8; c++) { float d = h[8 + c] - m; var += d * d; }
    var *= 0.125f;
    float inv = rsqrtf(var + 1e-5f);

    size_t b_ = P >> 16, pp = P & 65535;
    float* nb = g_n + (b_ << 19) + pp;
#pragma unroll
    for (int c = 0; c < 8; c++)
        nb[(size_t)c << 16] = (h[8 + c] - m) * inv * cgam[c] + cbet[c];
}

// ---------------------------------------------------------------------------
// Kernel B: one block = one (b,h) row; 128 threads, pixel pair (2t, 2t+1)
// packed in f32x2 lanes. dw 3x3 from smem row tile; pw/GEMM2 from constants.
// ---------------------------------------------------------------------------
__global__ void __launch_bounds__(128) kB(float* __restrict__ out) {
    __shared__ __align__(16) float ns[8][3][264];   // halo cols 0 and 257 zeroed

    int t = threadIdx.x;
    int b_ = blockIdx.x >> 8;
    int h  = blockIdx.x & 255;
    int w0 = 2 * t;

    // prefetch x1 (DRAM latency hidden behind smem fill + conv)
    size_t P0 = ((size_t)b_ << 16) + ((size_t)h << 8) + (size_t)w0;
    const float4* x1v = (const float4*)(g_x1 + P0 * 8);
    float4 XA = x1v[0], XB = x1v[1], XC = x1v[2], XD = x1v[3];

    const float* nbase = g_n + ((size_t)b_ << 19);
#pragma unroll
    for (int c = 0; c < 8; c++) {
#pragma unroll
        for (int r = 0; r < 3; r++) {
            int hs = h + r - 1;
            float2 v = make_float2(0.f, 0.f);
            if ((unsigned)hs < 256u)
                v = ((const float2*)(nbase + ((size_t)c << 16) + ((size_t)hs << 8)))[t];
            ns[c][r][1 + w0] = v.x;
            ns[c][r][2 + w0] = v.y;
        }
    }
    if (t == 0) {
#pragma unroll
        for (int c = 0; c < 8; c++)
#pragma unroll
            for (int r = 0; r < 3; r++) { ns[c][r][0] = 0.f; ns[c][r][257] = 0.f; }
    }
    __syncthreads();

    // depthwise 3x3 (SAME)
    ULL spp[8], ncp[8];
#pragma unroll
    for (int c = 0; c < 8; c++) {
        ULL acc = 0ULL, center = 0ULL;
#pragma unroll
        for (int r = 0; r < 3; r++) {
            ULL v01 = *(const ULL*)&ns[c][r][w0];       // (w0-1, w0)
            ULL v23 = *(const ULL*)&ns[c][r][w0 + 2];   // (w0+1, w0+2)
            ULL v12 = (v01 >> 32) | (v23 << 32);        // (w0,   w0+1)
            float wa = cdw[c * 9 + r * 3 + 0];
            float wb = cdw[c * 9 + r * 3 + 1];
            float wc = cdw[c * 9 + r * 3 + 2];
            acc = f2fma(v01, pk(wa, wa), acc);
            acc = f2fma(v12, pk(wb, wb), acc);
            acc = f2fma(v23, pk(wc, wc), acc);
            if (r == 1) center = v12;
        }
        spp[c] = f2add(acc, pk(cdwb[c], cdwb[c]));
        ncp[c] = center;
    }

    // pointwise 1x1
    ULL chp[8];
#pragma unroll
    for (int c = 0; c < 8; c++) {
        ULL a = pk(cpwb[c], cpwb[c]);
#pragma unroll
        for (int c2 = 0; c2 < 8; c2++) {
            float w = cpw[c * 8 + c2];
            a = f2fma(ncp[c2], pk(w, w), a);
        }
        chp[c] = a;
    }

    // gate: g = x1 * sp * ch   (lanes = the two pixels)
    float x10[8] = {XA.x, XA.y, XA.z, XA.w, XB.x, XB.y, XB.z, XB.w};
    float x11[8] = {XC.x, XC.y, XC.z, XC.w, XD.x, XD.y, XD.z, XD.w};
    ULL gp[8];
#pragma unroll
    for (int c = 0; c < 8; c++)
        gp[c] = f2mul(pk(x10[c], x11[c]), f2mul(spp[c], chp[c]));

    // GEMM2 in 4 quarters of 12 outputs (lower live regs)
    float* ob = out + (((size_t)b_ * 48) << 16) + ((size_t)h << 8) + (size_t)w0;
#pragma unroll
    for (int q = 0; q < 4; q++) {
        ULL o0[6], o1[6];
#pragma unroll
        for (int j = 0; j < 6; j++) { o0[j] = cb2p[q * 6 + j]; o1[j] = o0[j]; }
#pragma unroll
        for (int c = 0; c < 8; c++) {
            float g0, g1; upk(gp[c], g0, g1);
            ULL gb0 = pk(g0, g0), gb1 = pk(g1, g1);
#pragma unroll
            for (int j = 0; j < 6; j++) {
                ULL wv = cW2p[c * 24 + q * 6 + j];
                o0[j] = f2fma(gb0, wv, o0[j]);
                o1[j] = f2fma(gb1, wv, o1[j]);
            }
        }
#pragma unroll
        for (int j = 0; j < 6; j++) {
            float p00, p01, p10, p11;
            upk(o0[j], p00, p01);   // px0: d = d0, d0+1
            upk(o1[j], p10, p11);   // px1
            int d0 = q * 12 + 2 * j;
            *((float2*)(ob + ((size_t)d0 << 16)))       = make_float2(p00, p10);
            *((float2*)(ob + ((size_t)(d0 + 1) << 16))) = make_float2(p01, p11);
        }
    }
}

// ---------------------------------------------------------------------------
extern "C" void kernel_launch(void* const* d_in, const int* in_sizes, int n_in,
                              void* d_out, int out_size) {
    const float* x = (const float*)d_in[0];
    float* out = (float*)d_out;

    // weights -> constant memory (async D2D; graph-capturable memcpy nodes)
    cudaMemcpyToSymbolAsync(cW1p, d_in[1], 768 * 4, 0, cudaMemcpyDeviceToDevice);
    cudaMemcpyToSymbolAsync(cb1,  d_in[2], 16 * 4,  0, cudaMemcpyDeviceToDevice);
    cudaMemcpyToSymbolAsync(cgam, d_in[3], 8 * 4,   0, cudaMemcpyDeviceToDevice);
    cudaMemcpyToSymbolAsync(cbet, d_in[4], 8 * 4,   0, cudaMemcpyDeviceToDevice);
    cudaMemcpyToSymbolAsync(cdw,  d_in[5], 72 * 4,  0, cudaMemcpyDeviceToDevice);
    cudaMemcpyToSymbolAsync(cdwb, d_in[6], 8 * 4,   0, cudaMemcpyDeviceToDevice);
    cudaMemcpyToSymbolAsync(cpw,  d_in[7], 64 * 4,  0, cudaMemcpyDeviceToDevice);
    cudaMemcpyToSymbolAsync(cpwb, d_in[8], 8 * 4,   0, cudaMemcpyDeviceToDevice);
    cudaMemcpyToSymbolAsync(cW2p, d_in[9], 384 * 4, 0, cudaMemcpyDeviceToDevice);
    cudaMemcpyToSymbolAsync(cb2p, d_in[10], 48 * 4, 0, cudaMemcpyDeviceToDevice);

    kA<<<8192, 128>>>(x);
    kB<<<4096, 128>>>(out);
}